// round 9
// baseline (speedup 1.0000x reference)
#include <cuda_runtime.h>
#include <math.h>
#include <stdint.h>

#define B_  4
#define C_  256
#define N_  4096
#define CQ_ 64
#define SQRT_LOG2E 1.2011224087864498f   // sqrt(log2(e))

// ---------------- scratch (static __device__ — no allocations allowed) ---------
__device__ float g_P[B_*CQ_*N_];                 // P' = sqrt(log2e) * w_qk @ x (4 MB)
__device__ float g_V[B_*C_*N_];                  // V' = tf32r((w_v@x+b)*rinv)  (16 MB)
__device__ float g_E[(long long)B_*N_*N_];       // E = tf32r(2^(S'-c'_n))      (1.07 GB)
__device__ float g_R[B_*C_*N_];                  // x - nf                      (16 MB)
__device__ float g_diag[B_*N_];                  // c'_n = ||P'_n||^2
__device__ float g_rinv[B_*N_];                  // 1 / rowsum

// ---------------- helpers -------------------------------------------------------
__device__ __forceinline__ uint32_t f2tf(float x) {
    uint32_t r;
    asm("cvt.rna.tf32.f32 %0, %1;" : "=r"(r) : "f"(x));
    return r;
}
__device__ __forceinline__ float tf32r(float x) { return __uint_as_float(f2tf(x)); }
__device__ __forceinline__ float ex2(float x) {
    float y;
    asm("ex2.approx.ftz.f32 %0, %1;" : "=f"(y) : "f"(x));
    return y;
}
__device__ __forceinline__ void mma_tf32(float* d,
    uint32_t a0, uint32_t a1, uint32_t a2, uint32_t a3,
    uint32_t b0, uint32_t b1)
{
    asm("mma.sync.aligned.m16n8k8.row.col.f32.tf32.tf32.f32 "
        "{%0,%1,%2,%3}, {%4,%5,%6,%7}, {%8,%9}, {%0,%1,%2,%3};"
        : "+f"(d[0]), "+f"(d[1]), "+f"(d[2]), "+f"(d[3])
        : "r"(a0), "r"(a1), "r"(a2), "r"(a3), "r"(b0), "r"(b1));
}

// ---------------- generic batched SGEMM: C[b] = A(Mx256) * X[b](256xN_) --------
// mode 0: * sqrt(log2e)   (P projection)
// mode 2: +bias, BN(inference), ReLU   (final)
// mode 3: +bias, * rscale[n], tf32 round   (V projection)
__global__ __launch_bounds__(256) void gemm_kernel(
    const float* __restrict__ A,
    const float* __restrict__ X, long long xstride,
    float* __restrict__ Co, long long cstride,
    int mode,
    const float* __restrict__ bias,
    const float* __restrict__ gamma, const float* __restrict__ beta,
    const float* __restrict__ mean,  const float* __restrict__ var,
    const float* __restrict__ rscale)
{
    __shared__ float As[16][65];
    __shared__ float Bs[16][132];
    const int t  = threadIdx.x;
    const int n0 = blockIdx.x * 128;
    const int m0 = blockIdx.y * 64;
    const float* Xb = X + (long long)blockIdx.z * xstride;
    float*       Cb = Co + (long long)blockIdx.z * cstride;
    const int r0 = (t >> 5) << 3;
    const int c0 = (t & 31) << 2;

    float acc[8][4];
#pragma unroll
    for (int i = 0; i < 8; i++)
#pragma unroll
        for (int j = 0; j < 4; j++) acc[i][j] = 0.f;

    for (int k0 = 0; k0 < 256; k0 += 16) {
        {
            int row = t >> 2, kc = (t & 3) << 2;
            float4 v = *(const float4*)(A + (m0 + row) * 256 + k0 + kc);
            As[kc + 0][row] = v.x; As[kc + 1][row] = v.y;
            As[kc + 2][row] = v.z; As[kc + 3][row] = v.w;
        }
        {
            int kr = t >> 5, col = (t & 31) << 2;
            *(float4*)&Bs[kr][col]     = *(const float4*)(Xb + (long long)(k0 + kr)     * N_ + n0 + col);
            *(float4*)&Bs[kr + 8][col] = *(const float4*)(Xb + (long long)(k0 + kr + 8) * N_ + n0 + col);
        }
        __syncthreads();
#pragma unroll
        for (int k = 0; k < 16; k++) {
            float a[8];
#pragma unroll
            for (int i = 0; i < 8; i++) a[i] = As[k][r0 + i];
            float4 bv = *(float4*)&Bs[k][c0];
            float bb[4] = {bv.x, bv.y, bv.z, bv.w};
#pragma unroll
            for (int i = 0; i < 8; i++)
#pragma unroll
                for (int j = 0; j < 4; j++) acc[i][j] += a[i] * bb[j];
        }
        __syncthreads();
    }

    float4 rv = make_float4(1.f, 1.f, 1.f, 1.f);
    if (mode == 3)
        rv = *(const float4*)(rscale + (long long)blockIdx.z * N_ + n0 + c0);

#pragma unroll
    for (int i = 0; i < 8; i++) {
        int m = m0 + r0 + i;
        float v[4] = {acc[i][0], acc[i][1], acc[i][2], acc[i][3]};
        if (mode == 0) {
#pragma unroll
            for (int j = 0; j < 4; j++) v[j] *= SQRT_LOG2E;
        } else if (mode == 3) {
            float bb = bias[m];
            v[0] = tf32r((v[0] + bb) * rv.x);
            v[1] = tf32r((v[1] + bb) * rv.y);
            v[2] = tf32r((v[2] + bb) * rv.z);
            v[3] = tf32r((v[3] + bb) * rv.w);
        } else {   // mode 2
            float bb = bias[m];
            float sc = gamma[m] * rsqrtf(var[m] + 1e-5f);
            float mu = mean[m], bt = beta[m];
#pragma unroll
            for (int j = 0; j < 4; j++) v[j] = fmaxf((v[j] + bb - mu) * sc + bt, 0.f);
        }
        *(float4*)&Cb[(long long)m * N_ + n0 + c0] = make_float4(v[0], v[1], v[2], v[3]);
    }
}

// ---------------- diag: c'_n = sum_q P'[q][n]^2 --------------------------------
__global__ __launch_bounds__(256) void diag_kernel()
{
    int n = blockIdx.x * 256 + threadIdx.x;
    int b = blockIdx.y;
    const float* P = g_P + (long long)b * CQ_ * N_;
    float s = 0.f;
#pragma unroll
    for (int q = 0; q < CQ_; q++) {
        float p = P[(long long)q * N_ + n];
        s += p * p;
    }
    g_diag[b * N_ + n] = s;
}

// ---------------- pass 1: scores (3xTF32) + exp2 + store E + rowsum ------------
// grid (32, 4), 256 threads. Block owns n-tile 128; streams m in 64-tiles.
__global__ __launch_bounds__(256, 2) void score_exp_kernel()
{
    extern __shared__ float sh[];
    float* Pn  = sh;                 // [64][136]
    float* Pmh = Pn + 64 * 136;      // [64][72]
    float* Pml = Pmh + 64 * 72;      // [64][72]

    const int t    = threadIdx.x;
    const int w    = t >> 5;
    const int lane = t & 31;
    const int g    = lane >> 2;
    const int tig  = lane & 3;
    const int n0   = blockIdx.x * 128;
    const int b    = blockIdx.y;
    const float* P = g_P + (long long)b * CQ_ * N_;

#pragma unroll
    for (int i = 0; i < 8; i++) {
        int idx = t + i * 256; int r = idx >> 5, c4 = (idx & 31) << 2;
        *(float4*)&Pn[r * 136 + c4] = *(const float4*)(P + (long long)r * N_ + n0 + c4);
    }
    __syncthreads();

    // hoist A fragments (hi/lo splits) for the entire m loop
    uint32_t ah0[8], ah1[8], ah2[8], ah3[8];
    uint32_t al0[8], al1[8], al2[8], al3[8];
#pragma unroll
    for (int kc = 0; kc < 8; kc++) {
        float ar0 = Pn[(kc * 8 + tig)     * 136 + w * 16 + g];
        float ar1 = Pn[(kc * 8 + tig)     * 136 + w * 16 + g + 8];
        float ar2 = Pn[(kc * 8 + tig + 4) * 136 + w * 16 + g];
        float ar3 = Pn[(kc * 8 + tig + 4) * 136 + w * 16 + g + 8];
        ah0[kc] = f2tf(ar0); ah1[kc] = f2tf(ar1); ah2[kc] = f2tf(ar2); ah3[kc] = f2tf(ar3);
        al0[kc] = __float_as_uint(ar0 - __uint_as_float(ah0[kc]));
        al1[kc] = __float_as_uint(ar1 - __uint_as_float(ah1[kc]));
        al2[kc] = __float_as_uint(ar2 - __uint_as_float(ah2[kc]));
        al3[kc] = __float_as_uint(ar3 - __uint_as_float(ah3[kc]));
    }

    const int r0 = w * 16 + g, r1 = r0 + 8;
    const float c0 = g_diag[b * N_ + n0 + r0];
    const float c1 = g_diag[b * N_ + n0 + r1];
    float* E0 = g_E + ((long long)b * N_ + n0 + r0) * N_;
    float* E1 = g_E + ((long long)b * N_ + n0 + r1) * N_;
    float rsum0 = 0.f, rsum1 = 0.f;

    for (int m0t = 0; m0t < N_; m0t += 64) {
        __syncthreads();
#pragma unroll
        for (int i = 0; i < 4; i++) {
            int idx = t + i * 256; int r = idx >> 4, c4 = (idx & 15) << 2;
            float4 v = *(const float4*)(P + (long long)r * N_ + m0t + c4);
            float4 h; h.x = tf32r(v.x); h.y = tf32r(v.y); h.z = tf32r(v.z); h.w = tf32r(v.w);
            float4 l; l.x = v.x - h.x; l.y = v.y - h.y; l.z = v.z - h.z; l.w = v.w - h.w;
            *(float4*)&Pmh[r * 72 + c4] = h;
            *(float4*)&Pml[r * 72 + c4] = l;
        }
        __syncthreads();

        float s[8][4];
#pragma unroll
        for (int j = 0; j < 8; j++) {
            s[j][0] = -c0; s[j][1] = -c0; s[j][2] = -c1; s[j][3] = -c1;
        }

#pragma unroll
        for (int kc = 0; kc < 8; kc++) {
#pragma unroll
            for (int j = 0; j < 8; j++) {
                int col = j * 8 + g;
                uint32_t bh0 = __float_as_uint(Pmh[(kc * 8 + tig)     * 72 + col]);
                uint32_t bh1 = __float_as_uint(Pmh[(kc * 8 + tig + 4) * 72 + col]);
                uint32_t bl0 = __float_as_uint(Pml[(kc * 8 + tig)     * 72 + col]);
                uint32_t bl1 = __float_as_uint(Pml[(kc * 8 + tig + 4) * 72 + col]);
                mma_tf32(s[j], ah0[kc], ah1[kc], ah2[kc], ah3[kc], bh0, bh1);
                mma_tf32(s[j], ah0[kc], ah1[kc], ah2[kc], ah3[kc], bl0, bl1);
                mma_tf32(s[j], al0[kc], al1[kc], al2[kc], al3[kc], bh0, bh1);
            }
        }

        // e = 2^(S' - c'), tf32-rounded; store E + accumulate rowsum
#pragma unroll
        for (int j = 0; j < 8; j++) {
            float e0 = tf32r(ex2(s[j][0]));
            float e1 = tf32r(ex2(s[j][1]));
            float e2 = tf32r(ex2(s[j][2]));
            float e3 = tf32r(ex2(s[j][3]));
            rsum0 += e0 + e1;
            rsum1 += e2 + e3;
            int m = m0t + j * 8 + 2 * tig;
            *(float2*)&E0[m] = make_float2(e0, e1);
            *(float2*)&E1[m] = make_float2(e2, e3);
        }
    }

    rsum0 += __shfl_xor_sync(0xffffffffu, rsum0, 1);
    rsum0 += __shfl_xor_sync(0xffffffffu, rsum0, 2);
    rsum1 += __shfl_xor_sync(0xffffffffu, rsum1, 1);
    rsum1 += __shfl_xor_sync(0xffffffffu, rsum1, 2);
    if (tig == 0) {
        g_rinv[b * N_ + n0 + r0] = 1.0f / rsum0;
        g_rinv[b * N_ + n0 + r1] = 1.0f / rsum1;
    }
}

// ---------------- pass 2: AV GEMM + colsum + fused residual --------------------
// grid (64, 4), 512 threads. Block: m-tile 64, full C=256, streams n in 64-chunks.
// Warp tile 32c x 32m (B-frags shared by the two c-subtiles). Epilogue writes
// R = x - acc/(1e-9 + colsum) directly.
__global__ __launch_bounds__(512, 1) void av_kernel(const float* __restrict__ x)
{
    extern __shared__ float sh[];
    float* Es   = sh;                // [64][72]  E[n-chunk, m-tile]
    float* Vs   = Es + 64 * 72;      // [256][68] V'[:, n-chunk]
    float* rs   = Vs + 256 * 68;     // [64] rinv
    float* part = rs + 64;           // [512] colsum partials
    float* ci   = part + 512;        // [64] 1/(1e-9+colsum)

    const int t    = threadIdx.x;
    const int w    = t >> 5;
    const int lane = t & 31;
    const int g    = lane >> 2;
    const int tig  = lane & 3;
    const int cb   = (w & 7) * 32;   // c base
    const int mh   = (w >> 3) * 32;  // m half
    const int m0   = blockIdx.x * 64;
    const int b    = blockIdx.y;
    const int q    = t >> 6, mq = t & 63;

    const float* E    = g_E + (long long)b * N_ * N_;
    const float* V    = g_V + (long long)b * C_ * N_;
    const float* rinv = g_rinv + b * N_;

    float acc[2][4][4];
#pragma unroll
    for (int s2 = 0; s2 < 2; s2++)
#pragma unroll
        for (int j = 0; j < 4; j++)
#pragma unroll
            for (int k = 0; k < 4; k++) acc[s2][j][k] = 0.f;
    float csum = 0.f;

    for (int n0 = 0; n0 < N_; n0 += 64) {
        __syncthreads();
        if (t < 64) rs[t] = rinv[n0 + t];
#pragma unroll
        for (int i = 0; i < 2; i++) {    // Es 64x64
            int idx = t + i * 512; int r = idx >> 4, c4 = (idx & 15) << 2;
            *(float4*)&Es[r * 72 + c4] = *(const float4*)(E + (long long)(n0 + r) * N_ + m0 + c4);
        }
#pragma unroll
        for (int i = 0; i < 8; i++) {    // Vs 256x64
            int idx = t + i * 512; int r = idx >> 4, c4 = (idx & 15) << 2;
            *(float4*)&Vs[r * 68 + c4] = *(const float4*)(V + (long long)r * N_ + n0 + c4);
        }
        __syncthreads();

        // colsum partial: csum(q over n-subchunks, mq)
#pragma unroll
        for (int nn = 0; nn < 8; nn++)
            csum += rs[q * 8 + nn] * Es[(q * 8 + nn) * 72 + mq];

        // MMA: acc[c 32][m 32] += V' @ E
#pragma unroll
        for (int nc = 0; nc < 64; nc += 8) {
            uint32_t bf0[4], bf1[4];
#pragma unroll
            for (int j = 0; j < 4; j++) {
                bf0[j] = __float_as_uint(Es[(nc + tig)     * 72 + mh + j * 8 + g]);
                bf1[j] = __float_as_uint(Es[(nc + tig + 4) * 72 + mh + j * 8 + g]);
            }
#pragma unroll
            for (int s2 = 0; s2 < 2; s2++) {
                int ca = cb + s2 * 16 + g;
                uint32_t a0 = __float_as_uint(Vs[ca * 68 + nc + tig]);
                uint32_t a1 = __float_as_uint(Vs[(ca + 8) * 68 + nc + tig]);
                uint32_t a2 = __float_as_uint(Vs[ca * 68 + nc + tig + 4]);
                uint32_t a3 = __float_as_uint(Vs[(ca + 8) * 68 + nc + tig + 4]);
#pragma unroll
                for (int j = 0; j < 4; j++)
                    mma_tf32(acc[s2][j], a0, a1, a2, a3, bf0[j], bf1[j]);
            }
        }
    }

    __syncthreads();
    part[q * 64 + mq] = csum;
    __syncthreads();
    if (t < 64) {
        float s = 1e-9f;
#pragma unroll
        for (int qq = 0; qq < 8; qq++) s += part[qq * 64 + t];
        ci[t] = 1.0f / s;
    }
    __syncthreads();

    float* R = g_R + (long long)b * C_ * N_;
    const float* xb = x + (long long)b * C_ * N_;
#pragma unroll
    for (int j = 0; j < 4; j++) {
        int mm = mh + j * 8 + 2 * tig;
        float i0 = ci[mm], i1 = ci[mm + 1];
        long long m = m0 + mm;
#pragma unroll
        for (int s2 = 0; s2 < 2; s2++) {
            int ca = cb + s2 * 16 + g, cc = ca + 8;
            float2 xa = *(const float2*)(xb + (long long)ca * N_ + m);
            float2 xc = *(const float2*)(xb + (long long)cc * N_ + m);
            *(float2*)(R + (long long)ca * N_ + m) =
                make_float2(xa.x - acc[s2][j][0] * i0, xa.y - acc[s2][j][1] * i1);
            *(float2*)(R + (long long)cc * N_ + m) =
                make_float2(xc.x - acc[s2][j][2] * i0, xc.y - acc[s2][j][3] * i1);
        }
    }
}

// -------------------------------------------------------------------------------
#define SCORE_SMEM ((64 * 136 + 2 * 64 * 72) * 4)
#define AV_SMEM    ((64 * 72 + 256 * 68 + 64 + 512 + 64) * 4)

extern "C" void kernel_launch(void* const* d_in, const int* in_sizes, int n_in,
                              void* d_out, int out_size)
{
    const float* x       = (const float*)d_in[0];
    const float* w_qk    = (const float*)d_in[1];
    const float* w_v     = (const float*)d_in[2];
    const float* b_v     = (const float*)d_in[3];
    const float* w_trans = (const float*)d_in[4];
    const float* b_trans = (const float*)d_in[5];
    const float* gamma   = (const float*)d_in[6];
    const float* beta    = (const float*)d_in[7];
    const float* mean    = (const float*)d_in[8];
    const float* var     = (const float*)d_in[9];
    float* out = (float*)d_out;

    cudaFuncSetAttribute(score_exp_kernel, cudaFuncAttributeMaxDynamicSharedMemorySize, SCORE_SMEM);
    cudaFuncSetAttribute(av_kernel,        cudaFuncAttributeMaxDynamicSharedMemorySize, AV_SMEM);

    void *pP, *pV, *pR, *pRi;
    cudaGetSymbolAddress(&pP,  g_P);
    cudaGetSymbolAddress(&pV,  g_V);
    cudaGetSymbolAddress(&pR,  g_R);
    cudaGetSymbolAddress(&pRi, g_rinv);

    // P' = sqrt(log2e) * w_qk @ x   (M=64)
    gemm_kernel<<<dim3(32, 1, 4), 256>>>(w_qk, x, (long long)C_ * N_,
                                         (float*)pP, (long long)CQ_ * N_,
                                         0, nullptr, nullptr, nullptr, nullptr, nullptr, nullptr);
    // diag c'_n
    diag_kernel<<<dim3(16, 4), 256>>>();
    // E + rowsum (scores once)
    score_exp_kernel<<<dim3(32, 4), 256, SCORE_SMEM>>>();
    // V' = tf32r((w_v @ x + b_v) * rinv)   (M=256)
    gemm_kernel<<<dim3(32, 4, 4), 256>>>(w_v, x, (long long)C_ * N_,
                                         (float*)pV, (long long)C_ * N_,
                                         3, b_v, nullptr, nullptr, nullptr, nullptr,
                                         (const float*)pRi);
    // AV GEMM + colsum + fused residual -> R
    av_kernel<<<dim3(64, 4), 512, AV_SMEM>>>(x);
    // out = ReLU(BN(w_trans @ R + b_trans))
    gemm_kernel<<<dim3(32, 4, 4), 256>>>(w_trans, (const float*)pR, (long long)C_ * N_,
                                         out, (long long)C_ * N_,
                                         2, b_trans, gamma, beta, mean, var, nullptr);
}

// round 10
// speedup vs baseline: 1.4604x; 1.4604x over previous
#include <cuda_runtime.h>
#include <math.h>
#include <stdint.h>

#define B_  4
#define C_  256
#define N_  4096
#define CQ_ 64
#define SQRT_LOG2E 1.2011224087864498f   // sqrt(log2(e))

// ---------------- scratch (static __device__ — no allocations allowed) ---------
__device__ float g_P[B_*CQ_*N_];     // P' = sqrt(log2e) * w_qk @ x  (4 MB)
__device__ float g_V[B_*C_*N_];      // V' = tf32r(w_v @ x + b_v)    (16 MB)
__device__ float g_R[B_*C_*N_];      // x - new_features             (16 MB)
__device__ float g_diag[B_*N_];      // c'_n = ||P'_n||^2
__device__ float g_rinv[B_*N_];      // 1 / rowsum

// ---------------- helpers -------------------------------------------------------
__device__ __forceinline__ uint32_t f2tf(float x) {
    uint32_t r;
    asm("cvt.rna.tf32.f32 %0, %1;" : "=r"(r) : "f"(x));
    return r;
}
__device__ __forceinline__ float tf32r(float x) { return __uint_as_float(f2tf(x)); }
__device__ __forceinline__ float ex2(float x) {
    float y;
    asm("ex2.approx.ftz.f32 %0, %1;" : "=f"(y) : "f"(x));
    return y;
}
__device__ __forceinline__ void mma_tf32(float* d,
    uint32_t a0, uint32_t a1, uint32_t a2, uint32_t a3,
    uint32_t b0, uint32_t b1)
{
    asm("mma.sync.aligned.m16n8k8.row.col.f32.tf32.tf32.f32 "
        "{%0,%1,%2,%3}, {%4,%5,%6,%7}, {%8,%9}, {%0,%1,%2,%3};"
        : "+f"(d[0]), "+f"(d[1]), "+f"(d[2]), "+f"(d[3])
        : "r"(a0), "r"(a1), "r"(a2), "r"(a3), "r"(b0), "r"(b1));
}

// ---------------- fp32 FFMA GEMM (P projection only): scaled by sqrt(log2e) ----
__global__ __launch_bounds__(256) void gemm_kernel(
    const float* __restrict__ A,
    const float* __restrict__ X, long long xstride,
    float* __restrict__ Co, long long cstride)
{
    __shared__ float As[16][65];
    __shared__ float Bs[16][132];
    const int t  = threadIdx.x;
    const int n0 = blockIdx.x * 128;
    const int m0 = blockIdx.y * 64;
    const float* Xb = X + (long long)blockIdx.z * xstride;
    float*       Cb = Co + (long long)blockIdx.z * cstride;
    const int r0 = (t >> 5) << 3;
    const int c0 = (t & 31) << 2;

    float acc[8][4];
#pragma unroll
    for (int i = 0; i < 8; i++)
#pragma unroll
        for (int j = 0; j < 4; j++) acc[i][j] = 0.f;

    for (int k0 = 0; k0 < 256; k0 += 16) {
        {
            int row = t >> 2, kc = (t & 3) << 2;
            float4 v = *(const float4*)(A + (m0 + row) * 256 + k0 + kc);
            As[kc + 0][row] = v.x; As[kc + 1][row] = v.y;
            As[kc + 2][row] = v.z; As[kc + 3][row] = v.w;
        }
        {
            int kr = t >> 5, col = (t & 31) << 2;
            *(float4*)&Bs[kr][col]     = *(const float4*)(Xb + (long long)(k0 + kr)     * N_ + n0 + col);
            *(float4*)&Bs[kr + 8][col] = *(const float4*)(Xb + (long long)(k0 + kr + 8) * N_ + n0 + col);
        }
        __syncthreads();
#pragma unroll
        for (int k = 0; k < 16; k++) {
            float a[8];
#pragma unroll
            for (int i = 0; i < 8; i++) a[i] = As[k][r0 + i];
            float4 bv = *(float4*)&Bs[k][c0];
            float bb[4] = {bv.x, bv.y, bv.z, bv.w};
#pragma unroll
            for (int i = 0; i < 8; i++)
#pragma unroll
                for (int j = 0; j < 4; j++) acc[i][j] += a[i] * bb[j];
        }
        __syncthreads();
    }

#pragma unroll
    for (int i = 0; i < 8; i++) {
        int m = m0 + r0 + i;
        *(float4*)&Cb[(long long)m * N_ + n0 + c0] =
            make_float4(acc[i][0] * SQRT_LOG2E, acc[i][1] * SQRT_LOG2E,
                        acc[i][2] * SQRT_LOG2E, acc[i][3] * SQRT_LOG2E);
    }
}

// ---------------- tf32-MMA GEMM: out[b] = W(256x256) @ X[b] + epilogue ---------
// W split hi/lo (2 MMA, exact weights); X tf32-rounded at load.
// mode 1: +bias, tf32 round (V projection). mode 2: +bias, BN, ReLU (final).
__global__ __launch_bounds__(512) void tgemm_kernel(
    const float* __restrict__ W,
    const float* __restrict__ X, long long xstride,
    float* __restrict__ Co, long long cstride,
    int mode,
    const float* __restrict__ bias,
    const float* __restrict__ gamma, const float* __restrict__ beta,
    const float* __restrict__ mean,  const float* __restrict__ var)
{
    extern __shared__ float sh[];
    float* Wh = sh;                  // [256][68]
    float* Wl = Wh + 256 * 68;       // [256][68]
    float* Xs = Wl + 256 * 68;       // [64][136]

    const int t    = threadIdx.x;
    const int w    = t >> 5;
    const int lane = t & 31;
    const int g    = lane >> 2;
    const int tig  = lane & 3;
    const int mg   = (w & 3) * 64;   // warp m-group (64 rows)
    const int ng   = (w >> 2) * 32;  // warp n-group (32 cols)
    const int n0   = blockIdx.x * 128;
    const float* Xb = X + (long long)blockIdx.y * xstride;
    float*       Cb = Co + (long long)blockIdx.y * cstride;

    float acc[4][4][4];   // [m-frag 16][n-frag 8][quad]
#pragma unroll
    for (int i = 0; i < 4; i++)
#pragma unroll
        for (int j = 0; j < 4; j++)
#pragma unroll
            for (int q = 0; q < 4; q++) acc[i][j][q] = 0.f;

    for (int kc0 = 0; kc0 < 256; kc0 += 64) {
        __syncthreads();
#pragma unroll
        for (int i = 0; i < 8; i++) {       // W tile 256x64, split
            int idx = t + i * 512; int r = idx >> 4, c4 = (idx & 15) << 2;
            float4 v = *(const float4*)(W + r * 256 + kc0 + c4);
            float4 h; h.x = tf32r(v.x); h.y = tf32r(v.y); h.z = tf32r(v.z); h.w = tf32r(v.w);
            float4 l; l.x = v.x - h.x; l.y = v.y - h.y; l.z = v.z - h.z; l.w = v.w - h.w;
            *(float4*)&Wh[r * 68 + c4] = h;
            *(float4*)&Wl[r * 68 + c4] = l;
        }
#pragma unroll
        for (int i = 0; i < 4; i++) {       // X tile 64x128, tf32-rounded
            int idx = t + i * 512; int r = idx >> 5, c4 = (idx & 31) << 2;
            float4 v = *(const float4*)(Xb + (long long)(kc0 + r) * N_ + n0 + c4);
            v.x = tf32r(v.x); v.y = tf32r(v.y); v.z = tf32r(v.z); v.w = tf32r(v.w);
            *(float4*)&Xs[r * 136 + c4] = v;
        }
        __syncthreads();

#pragma unroll
        for (int kk = 0; kk < 64; kk += 8) {
            uint32_t b0[4], b1[4];
#pragma unroll
            for (int j = 0; j < 4; j++) {
                b0[j] = __float_as_uint(Xs[(kk + tig)     * 136 + ng + j * 8 + g]);
                b1[j] = __float_as_uint(Xs[(kk + tig + 4) * 136 + ng + j * 8 + g]);
            }
#pragma unroll
            for (int i = 0; i < 4; i++) {
                int row = mg + i * 16;
                uint32_t ah0 = __float_as_uint(Wh[(row + g)     * 68 + kk + tig]);
                uint32_t ah1 = __float_as_uint(Wh[(row + g + 8) * 68 + kk + tig]);
                uint32_t ah2 = __float_as_uint(Wh[(row + g)     * 68 + kk + tig + 4]);
                uint32_t ah3 = __float_as_uint(Wh[(row + g + 8) * 68 + kk + tig + 4]);
                uint32_t al0 = __float_as_uint(Wl[(row + g)     * 68 + kk + tig]);
                uint32_t al1 = __float_as_uint(Wl[(row + g + 8) * 68 + kk + tig]);
                uint32_t al2 = __float_as_uint(Wl[(row + g)     * 68 + kk + tig + 4]);
                uint32_t al3 = __float_as_uint(Wl[(row + g + 8) * 68 + kk + tig + 4]);
#pragma unroll
                for (int j = 0; j < 4; j++) {
                    mma_tf32(acc[i][j], ah0, ah1, ah2, ah3, b0[j], b1[j]);
                    mma_tf32(acc[i][j], al0, al1, al2, al3, b0[j], b1[j]);
                }
            }
        }
    }

#pragma unroll
    for (int i = 0; i < 4; i++) {
        int m0r = mg + i * 16 + g;       // rows m0r, m0r+8
#pragma unroll
        for (int j = 0; j < 4; j++) {
            long long m = n0 + ng + j * 8 + 2 * tig;
            float v0 = acc[i][j][0], v1 = acc[i][j][1];
            float v2 = acc[i][j][2], v3 = acc[i][j][3];
            if (mode == 1) {
                float b0v = bias[m0r], b1v = bias[m0r + 8];
                v0 = tf32r(v0 + b0v); v1 = tf32r(v1 + b0v);
                v2 = tf32r(v2 + b1v); v3 = tf32r(v3 + b1v);
            } else {
                float b0v = bias[m0r], b1v = bias[m0r + 8];
                float s0 = gamma[m0r]     * rsqrtf(var[m0r]     + 1e-5f);
                float s1 = gamma[m0r + 8] * rsqrtf(var[m0r + 8] + 1e-5f);
                float u0 = mean[m0r], u1 = mean[m0r + 8];
                float t0 = beta[m0r], t1 = beta[m0r + 8];
                v0 = fmaxf((v0 + b0v - u0) * s0 + t0, 0.f);
                v1 = fmaxf((v1 + b0v - u0) * s0 + t0, 0.f);
                v2 = fmaxf((v2 + b1v - u1) * s1 + t1, 0.f);
                v3 = fmaxf((v3 + b1v - u1) * s1 + t1, 0.f);
            }
            *(float2*)&Cb[(long long)m0r * N_ + m]       = make_float2(v0, v1);
            *(float2*)&Cb[(long long)(m0r + 8) * N_ + m] = make_float2(v2, v3);
        }
    }
}

// ---------------- diag: c'_n = sum_q P'[q][n]^2 --------------------------------
__global__ __launch_bounds__(256) void diag_kernel()
{
    int n = blockIdx.x * 256 + threadIdx.x;
    int b = blockIdx.y;
    const float* P = g_P + (long long)b * CQ_ * N_;
    float s = 0.f;
#pragma unroll
    for (int q = 0; q < CQ_; q++) {
        float p = P[(long long)q * N_ + n];
        s += p * p;
    }
    g_diag[b * N_ + n] = s;
}

// ---------------- rowsum: 3xTF32 scores + exp2 (diag-shifted), no max ----------
__global__ __launch_bounds__(256, 2) void rowsum_kernel()
{
    extern __shared__ float sh[];
    float* Pn  = sh;                 // [64][136]
    float* Pmh = Pn + 64 * 136;      // [64][72]
    float* Pml = Pmh + 64 * 72;      // [64][72]

    const int t    = threadIdx.x;
    const int w    = t >> 5;
    const int lane = t & 31;
    const int g    = lane >> 2;
    const int tig  = lane & 3;
    const int n0   = blockIdx.x * 128;
    const int b    = blockIdx.y;
    const float* P = g_P + (long long)b * CQ_ * N_;

#pragma unroll
    for (int i = 0; i < 8; i++) {
        int idx = t + i * 256; int r = idx >> 5, c4 = (idx & 31) << 2;
        *(float4*)&Pn[r * 136 + c4] = *(const float4*)(P + (long long)r * N_ + n0 + c4);
    }
    __syncthreads();

    uint32_t ah0[8], ah1[8], ah2[8], ah3[8];
    uint32_t al0[8], al1[8], al2[8], al3[8];
#pragma unroll
    for (int kc = 0; kc < 8; kc++) {
        float ar0 = Pn[(kc * 8 + tig)     * 136 + w * 16 + g];
        float ar1 = Pn[(kc * 8 + tig)     * 136 + w * 16 + g + 8];
        float ar2 = Pn[(kc * 8 + tig + 4) * 136 + w * 16 + g];
        float ar3 = Pn[(kc * 8 + tig + 4) * 136 + w * 16 + g + 8];
        ah0[kc] = f2tf(ar0); ah1[kc] = f2tf(ar1); ah2[kc] = f2tf(ar2); ah3[kc] = f2tf(ar3);
        al0[kc] = __float_as_uint(ar0 - __uint_as_float(ah0[kc]));
        al1[kc] = __float_as_uint(ar1 - __uint_as_float(ah1[kc]));
        al2[kc] = __float_as_uint(ar2 - __uint_as_float(ah2[kc]));
        al3[kc] = __float_as_uint(ar3 - __uint_as_float(ah3[kc]));
    }

    const int r0 = w * 16 + g, r1 = r0 + 8;
    const float c0 = g_diag[b * N_ + n0 + r0];
    const float c1 = g_diag[b * N_ + n0 + r1];
    float rsum0 = 0.f, rsum1 = 0.f;

    for (int m0t = 0; m0t < N_; m0t += 64) {
        __syncthreads();
#pragma unroll
        for (int i = 0; i < 4; i++) {
            int idx = t + i * 256; int r = idx >> 4, c4 = (idx & 15) << 2;
            float4 v = *(const float4*)(P + (long long)r * N_ + m0t + c4);
            float4 h; h.x = tf32r(v.x); h.y = tf32r(v.y); h.z = tf32r(v.z); h.w = tf32r(v.w);
            float4 l; l.x = v.x - h.x; l.y = v.y - h.y; l.z = v.z - h.z; l.w = v.w - h.w;
            *(float4*)&Pmh[r * 72 + c4] = h;
            *(float4*)&Pml[r * 72 + c4] = l;
        }
        __syncthreads();

        float s[8][4];
#pragma unroll
        for (int j = 0; j < 8; j++) {
            s[j][0] = -c0; s[j][1] = -c0; s[j][2] = -c1; s[j][3] = -c1;
        }
#pragma unroll
        for (int kc = 0; kc < 8; kc++) {
#pragma unroll
            for (int j = 0; j < 8; j++) {
                int col = j * 8 + g;
                uint32_t bh0 = __float_as_uint(Pmh[(kc * 8 + tig)     * 72 + col]);
                uint32_t bh1 = __float_as_uint(Pmh[(kc * 8 + tig + 4) * 72 + col]);
                uint32_t bl0 = __float_as_uint(Pml[(kc * 8 + tig)     * 72 + col]);
                uint32_t bl1 = __float_as_uint(Pml[(kc * 8 + tig + 4) * 72 + col]);
                mma_tf32(s[j], ah0[kc], ah1[kc], ah2[kc], ah3[kc], bh0, bh1);
                mma_tf32(s[j], ah0[kc], ah1[kc], ah2[kc], ah3[kc], bl0, bl1);
                mma_tf32(s[j], al0[kc], al1[kc], al2[kc], al3[kc], bh0, bh1);
            }
        }
#pragma unroll
        for (int j = 0; j < 8; j++) {
            rsum0 += tf32r(ex2(s[j][0])) + tf32r(ex2(s[j][1]));
            rsum1 += tf32r(ex2(s[j][2])) + tf32r(ex2(s[j][3]));
        }
    }

    rsum0 += __shfl_xor_sync(0xffffffffu, rsum0, 1);
    rsum0 += __shfl_xor_sync(0xffffffffu, rsum0, 2);
    rsum1 += __shfl_xor_sync(0xffffffffu, rsum1, 1);
    rsum1 += __shfl_xor_sync(0xffffffffu, rsum1, 2);
    if (tig == 0) {
        g_rinv[b * N_ + n0 + r0] = 1.0f / rsum0;
        g_rinv[b * N_ + n0 + r1] = 1.0f / rsum1;
    }
}

// ---------------- fused attention: scores + exp + AV + colsum + residual -------
// grid (64, 4), 512 threads. Phase A: 3xTF32 S-tile (diag-shift init).
// Phase B: 32c x 32m warp tiles, full C=256 in one pass. Epilogue: R = x - M*ci.
__global__ __launch_bounds__(512, 1) void attn_kernel(const float* __restrict__ x)
{
    extern __shared__ float sh[];
    float* Pm   = sh;                    // [64][72]
    float* Pn   = Pm + 64 * 72;          // [64][136]
    float* Ae   = Pn + 64 * 136;         // [128][72]
    float* Vs   = Ae + 128 * 72;         // [256][132]
    float* sc   = Vs + 256 * 132;        // [128] diag shift
    float* sri  = sc + 128;              // [128] 1/rowsum
    float* part = sri + 128;             // [8][64] colsum partials
    float* ci   = part + 512;            // [64] 1/(1e-9+colsum)

    const int t    = threadIdx.x;
    const int w    = t >> 5;
    const int lane = t & 31;
    const int g    = lane >> 2;
    const int tig  = lane & 3;
    const int wn   = w & 7;              // phase A n-slice (16 rows)
    const int mh   = (w >> 3) * 32;      // phase A m-half (32 cols)
    const int wc   = (w & 7) * 32;       // phase B c-group (32 rows)
    const int wm   = (w >> 3) * 32;      // phase B m-half (32 cols)
    const int m0   = blockIdx.x * 64;
    const int b    = blockIdx.y;

    const float* P = g_P + (long long)b * CQ_ * N_;
    const float* V = g_V + (long long)b * C_  * N_;

#pragma unroll
    for (int i = 0; i < 2; i++) {   // Pm 64x64, once
        int idx = t + i * 512; int r = idx >> 4, c4 = (idx & 15) << 2;
        *(float4*)&Pm[r * 72 + c4] = *(const float4*)(P + (long long)r * N_ + m0 + c4);
    }

    float acc[2][4][4];
#pragma unroll
    for (int s2 = 0; s2 < 2; s2++)
#pragma unroll
        for (int j = 0; j < 4; j++)
#pragma unroll
            for (int q = 0; q < 4; q++) acc[s2][j][q] = 0.f;
    float csum = 0.f;

    for (int n0 = 0; n0 < N_; n0 += 128) {
        __syncthreads();   // S1
        if (n0 && t < 64) {
#pragma unroll
            for (int q = 0; q < 8; q++) csum += part[q * 64 + t];
        }

#pragma unroll
        for (int i = 0; i < 4; i++) {   // Pn 64x128
            int idx = t + i * 512; int r = idx >> 5, c4 = (idx & 31) << 2;
            *(float4*)&Pn[r * 136 + c4] = *(const float4*)(P + (long long)r * N_ + n0 + c4);
        }
#pragma unroll
        for (int i = 0; i < 16; i++) {  // Vs 256x128 (pre-rounded V')
            int idx = t + i * 512; int r = idx >> 5, c4 = (idx & 31) << 2;
            *(float4*)&Vs[r * 132 + c4] = *(const float4*)(V + (long long)r * N_ + n0 + c4);
        }
        if (t < 128) {
            sc[t]  = g_diag[b * N_ + n0 + t];
            sri[t] = g_rinv[b * N_ + n0 + t];
        }
        __syncthreads();   // S2

        // ---- phase A: s = Pn^T Pm - c (3xTF32, shift in accumulator init) ----
        const int r0 = wn * 16 + g, r1 = r0 + 8;
        const float c0v = sc[r0], c1v = sc[r1];
        float s[4][4];
#pragma unroll
        for (int j = 0; j < 4; j++) {
            s[j][0] = -c0v; s[j][1] = -c0v; s[j][2] = -c1v; s[j][3] = -c1v;
        }
#pragma unroll
        for (int kc = 0; kc < 64; kc += 8) {
            float ar0 = Pn[(kc + tig)     * 136 + wn * 16 + g];
            float ar1 = Pn[(kc + tig)     * 136 + wn * 16 + g + 8];
            float ar2 = Pn[(kc + tig + 4) * 136 + wn * 16 + g];
            float ar3 = Pn[(kc + tig + 4) * 136 + wn * 16 + g + 8];
            uint32_t ah0 = f2tf(ar0), ah1 = f2tf(ar1), ah2 = f2tf(ar2), ah3 = f2tf(ar3);
            uint32_t al0 = __float_as_uint(ar0 - __uint_as_float(ah0));
            uint32_t al1 = __float_as_uint(ar1 - __uint_as_float(ah1));
            uint32_t al2 = __float_as_uint(ar2 - __uint_as_float(ah2));
            uint32_t al3 = __float_as_uint(ar3 - __uint_as_float(ah3));
#pragma unroll
            for (int j = 0; j < 4; j++) {
                int col = mh + j * 8 + g;
                float br0 = Pm[(kc + tig)     * 72 + col];
                float br1 = Pm[(kc + tig + 4) * 72 + col];
                uint32_t bh0 = f2tf(br0), bh1 = f2tf(br1);
                uint32_t bl0 = __float_as_uint(br0 - __uint_as_float(bh0));
                uint32_t bl1 = __float_as_uint(br1 - __uint_as_float(bh1));
                mma_tf32(s[j], ah0, ah1, ah2, ah3, bh0, bh1);
                mma_tf32(s[j], ah0, ah1, ah2, ah3, bl0, bl1);
                mma_tf32(s[j], al0, al1, al2, al3, bh0, bh1);
            }
        }

        // exp2 + row-normalize -> Ae (tf32-rounded)
        {
            float ri0 = sri[r0], ri1 = sri[r1];
#pragma unroll
            for (int j = 0; j < 4; j++) {
                int col = mh + j * 8 + 2 * tig;
                float e0 = tf32r(ex2(s[j][0]) * ri0);
                float e1 = tf32r(ex2(s[j][1]) * ri0);
                float e2 = tf32r(ex2(s[j][2]) * ri1);
                float e3 = tf32r(ex2(s[j][3]) * ri1);
                *(float2*)&Ae[r0 * 72 + col] = make_float2(e0, e1);
                *(float2*)&Ae[r1 * 72 + col] = make_float2(e2, e3);
            }
        }
        __syncthreads();   // S3

        // colsum partials
        {
            int q = t >> 6, mq = t & 63;
            float p = 0.f;
#pragma unroll
            for (int nn = 0; nn < 16; nn++) p += Ae[(q * 16 + nn) * 72 + mq];
            part[q * 64 + mq] = p;
        }

        // ---- phase B: acc[32c][32m] += V' @ Ae ----
#pragma unroll
        for (int nc = 0; nc < 128; nc += 8) {
            uint32_t bf0[4], bf1[4];
#pragma unroll
            for (int j = 0; j < 4; j++) {
                bf0[j] = __float_as_uint(Ae[(nc + tig)     * 72 + wm + j * 8 + g]);
                bf1[j] = __float_as_uint(Ae[(nc + tig + 4) * 72 + wm + j * 8 + g]);
            }
#pragma unroll
            for (int s2 = 0; s2 < 2; s2++) {
                int ca = wc + s2 * 16 + g;
                uint32_t a0 = __float_as_uint(Vs[ca * 132 + nc + tig]);
                uint32_t a1 = __float_as_uint(Vs[(ca + 8) * 132 + nc + tig]);
                uint32_t a2 = __float_as_uint(Vs[ca * 132 + nc + tig + 4]);
                uint32_t a3 = __float_as_uint(Vs[(ca + 8) * 132 + nc + tig + 4]);
#pragma unroll
                for (int j = 0; j < 4; j++)
                    mma_tf32(acc[s2][j], a0, a1, a2, a3, bf0[j], bf1[j]);
            }
        }
    }

    __syncthreads();
    if (t < 64) {
#pragma unroll
        for (int q = 0; q < 8; q++) csum += part[q * 64 + t];
        ci[t] = 1.0f / (1e-9f + csum);
    }
    __syncthreads();

    // ---- epilogue: R = x - acc * ci ----
    float* R = g_R + (long long)b * C_ * N_;
    const float* xb = x + (long long)b * C_ * N_;
#pragma unroll
    for (int j = 0; j < 4; j++) {
        int mm = wm + j * 8 + 2 * tig;
        float i0 = ci[mm], i1 = ci[mm + 1];
        long long m = m0 + mm;
#pragma unroll
        for (int s2 = 0; s2 < 2; s2++) {
            int ca = wc + s2 * 16 + g, cc = ca + 8;
            float2 xa = *(const float2*)(xb + (long long)ca * N_ + m);
            float2 xc = *(const float2*)(xb + (long long)cc * N_ + m);
            *(float2*)(R + (long long)ca * N_ + m) =
                make_float2(xa.x - acc[s2][j][0] * i0, xa.y - acc[s2][j][1] * i1);
            *(float2*)(R + (long long)cc * N_ + m) =
                make_float2(xc.x - acc[s2][j][2] * i0, xc.y - acc[s2][j][3] * i1);
        }
    }
}

// -------------------------------------------------------------------------------
#define ROWSUM_SMEM ((64 * 136 + 2 * 64 * 72) * 4)
#define ATTN_SMEM   ((64 * 72 + 64 * 136 + 128 * 72 + 256 * 132 + 128 + 128 + 512 + 64) * 4)
#define TGEMM_SMEM  ((2 * 256 * 68 + 64 * 136) * 4)

extern "C" void kernel_launch(void* const* d_in, const int* in_sizes, int n_in,
                              void* d_out, int out_size)
{
    const float* x       = (const float*)d_in[0];
    const float* w_qk    = (const float*)d_in[1];
    const float* w_v     = (const float*)d_in[2];
    const float* b_v     = (const float*)d_in[3];
    const float* w_trans = (const float*)d_in[4];
    const float* b_trans = (const float*)d_in[5];
    const float* gamma   = (const float*)d_in[6];
    const float* beta    = (const float*)d_in[7];
    const float* mean    = (const float*)d_in[8];
    const float* var     = (const float*)d_in[9];
    float* out = (float*)d_out;

    cudaFuncSetAttribute(rowsum_kernel, cudaFuncAttributeMaxDynamicSharedMemorySize, ROWSUM_SMEM);
    cudaFuncSetAttribute(attn_kernel,   cudaFuncAttributeMaxDynamicSharedMemorySize, ATTN_SMEM);
    cudaFuncSetAttribute(tgemm_kernel,  cudaFuncAttributeMaxDynamicSharedMemorySize, TGEMM_SMEM);

    void *pP, *pV, *pR;
    cudaGetSymbolAddress(&pP, g_P);
    cudaGetSymbolAddress(&pV, g_V);
    cudaGetSymbolAddress(&pR, g_R);

    // P' = sqrt(log2e) * w_qk @ x   (fp32 FFMA, precision-critical)
    gemm_kernel<<<dim3(32, 1, 4), 256>>>(w_qk, x, (long long)C_ * N_,
                                         (float*)pP, (long long)CQ_ * N_);
    // c'_n = ||P'_n||^2
    diag_kernel<<<dim3(16, 4), 256>>>();
    // rowsum (scores pass 1, diag-shifted, no max)
    rowsum_kernel<<<dim3(32, 4), 256, ROWSUM_SMEM>>>();
    // V' = tf32r(w_v @ x + b_v)    (tf32 MMA, W-split)
    tgemm_kernel<<<dim3(32, 4), 512, TGEMM_SMEM>>>(w_v, x, (long long)C_ * N_,
                                                   (float*)pV, (long long)C_ * N_,
                                                   1, b_v, nullptr, nullptr, nullptr, nullptr);
    // fused attention (scores pass 2 + exp + AV + colsum + residual)
    attn_kernel<<<dim3(64, 4), 512, ATTN_SMEM>>>(x);
    // out = ReLU(BN(w_trans @ R + b_trans))   (tf32 MMA, W-split)
    tgemm_kernel<<<dim3(32, 4), 512, TGEMM_SMEM>>>(w_trans, (const float*)pR, (long long)C_ * N_,
                                                   out, (long long)C_ * N_,
                                                   2, b_trans, gamma, beta, mean, var);
}